// round 1
// baseline (speedup 1.0000x reference)
#include <cuda_runtime.h>
#include <math.h>

#define BB 8
#define NN 4096
#define MM 4096
#define DD 128

#define BK 16
#define PAD 132   // smem row stride in floats (k-major layout), breaks most STS conflicts

// Scratch (no allocations allowed -> __device__ globals)
__device__ unsigned int g_fwd[BB * MM];        // min over n of clamped squared dist, as uint bits
__device__ float g_x2[BB * NN];
__device__ float g_y2[BB * MM];
__device__ float g_bwd_part[32 * 32];          // per-block backward partial sums

// ---------------------------------------------------------------------------
__global__ void init_kernel() {
    int i = blockIdx.x * blockDim.x + threadIdx.x;
    if (i < BB * MM) g_fwd[i] = 0x7F800000u;   // +inf
}

// One warp per row: sum of squares of 128 floats
__global__ void norms_kernel(const float* __restrict__ X, const float* __restrict__ Y) {
    int w    = (blockIdx.x * blockDim.x + threadIdx.x) >> 5;
    int lane = threadIdx.x & 31;
    const float* p;
    float* dst;
    if (w < BB * NN) {
        p = X + (size_t)w * DD;
        dst = &g_x2[w];
    } else {
        int w2 = w - BB * NN;
        if (w2 >= BB * MM) return;
        p = Y + (size_t)w2 * DD;
        dst = &g_y2[w2];
    }
    float4 v = ((const float4*)p)[lane];
    float s = v.x * v.x + v.y * v.y + v.z * v.z + v.w * v.w;
    #pragma unroll
    for (int o = 16; o; o >>= 1) s += __shfl_xor_sync(0xffffffffu, s, o);
    if (lane == 0) *dst = s;
}

// ---------------------------------------------------------------------------
// Main: per (128n x 128m) tile, loop b=0..7. 256 threads, 8x8 outputs/thread.
__global__ __launch_bounds__(256, 1) void chamfer_main(const float* __restrict__ X,
                                                       const float* __restrict__ Y) {
    __shared__ float As[BK * PAD];
    __shared__ float Bs[BK * PAD];
    __shared__ unsigned int cmin[128];
    __shared__ float red[8];

    const int tid = threadIdx.x;
    const int tx = tid & 15, ty = tid >> 4;
    const int nTile = blockIdx.y * 128;
    const int mTile = blockIdx.x * 128;

    const int lr  = tid >> 2;   // 0..63 : tile row for loads
    const int lc4 = tid & 3;    // 0..3  : float4 column for loads

    const int n0 = ty * 4, n1 = 64 + ty * 4;
    const int m0 = tx * 4, m1 = 64 + tx * 4;

    float bmin[8][8];
    #pragma unroll
    for (int i = 0; i < 8; i++)
        #pragma unroll
        for (int j = 0; j < 8; j++) bmin[i][j] = INFINITY;

    for (int b = 0; b < BB; ++b) {
        const float* Xb = X + ((size_t)b * NN + nTile) * DD;
        const float* Yb = Y + ((size_t)b * MM + mTile) * DD;

        float acc[8][8];
        #pragma unroll
        for (int i = 0; i < 8; i++)
            #pragma unroll
            for (int j = 0; j < 8; j++) acc[i][j] = 0.f;

        for (int k0 = 0; k0 < DD; k0 += BK) {
            __syncthreads();
            #pragma unroll
            for (int h = 0; h < 2; ++h) {
                int r = lr + h * 64;
                float4 va = *(const float4*)(Xb + (size_t)r * DD + k0 + lc4 * 4);
                float4 vb = *(const float4*)(Yb + (size_t)r * DD + k0 + lc4 * 4);
                As[(lc4 * 4 + 0) * PAD + r] = va.x;
                As[(lc4 * 4 + 1) * PAD + r] = va.y;
                As[(lc4 * 4 + 2) * PAD + r] = va.z;
                As[(lc4 * 4 + 3) * PAD + r] = va.w;
                Bs[(lc4 * 4 + 0) * PAD + r] = vb.x;
                Bs[(lc4 * 4 + 1) * PAD + r] = vb.y;
                Bs[(lc4 * 4 + 2) * PAD + r] = vb.z;
                Bs[(lc4 * 4 + 3) * PAD + r] = vb.w;
            }
            __syncthreads();
            #pragma unroll
            for (int kk = 0; kk < BK; ++kk) {
                float4 a0 = *(const float4*)&As[kk * PAD + n0];
                float4 a1 = *(const float4*)&As[kk * PAD + n1];
                float4 b0 = *(const float4*)&Bs[kk * PAD + m0];
                float4 b1 = *(const float4*)&Bs[kk * PAD + m1];
                float ar[8] = {a0.x, a0.y, a0.z, a0.w, a1.x, a1.y, a1.z, a1.w};
                float br[8] = {b0.x, b0.y, b0.z, b0.w, b1.x, b1.y, b1.z, b1.w};
                #pragma unroll
                for (int i = 0; i < 8; i++)
                    #pragma unroll
                    for (int j = 0; j < 8; j++)
                        acc[i][j] = fmaf(ar[i], br[j], acc[i][j]);
            }
        }

        // init shared column-min buffer for this b
        if (tid < 128) cmin[tid] = 0x7F800000u;
        __syncthreads();

        float rx2[8], ry2[8];
        #pragma unroll
        for (int i = 0; i < 4; i++) {
            rx2[i]     = g_x2[b * NN + nTile + n0 + i];
            rx2[i + 4] = g_x2[b * NN + nTile + n1 + i];
        }
        #pragma unroll
        for (int j = 0; j < 4; j++) {
            ry2[j]     = g_y2[b * MM + mTile + m0 + j];
            ry2[j + 4] = g_y2[b * MM + mTile + m1 + j];
        }

        float colmin[8];
        #pragma unroll
        for (int j = 0; j < 8; j++) colmin[j] = INFINITY;

        #pragma unroll
        for (int i = 0; i < 8; i++) {
            #pragma unroll
            for (int j = 0; j < 8; j++) {
                float d2 = fmaf(-2.f, acc[i][j], rx2[i] + ry2[j]);
                d2 = fmaxf(d2, 0.f);
                bmin[i][j] = fminf(bmin[i][j], d2);
                colmin[j]  = fminf(colmin[j], d2);
            }
        }

        #pragma unroll
        for (int j = 0; j < 8; j++) {
            int ml = (j < 4) ? (m0 + j) : (m1 + j - 4);
            atomicMin(&cmin[ml], __float_as_uint(colmin[j]));
        }
        __syncthreads();
        if (tid < 128)
            atomicMin(&g_fwd[(size_t)b * MM + mTile + tid], cmin[tid]);
        // next b's k0-loop __syncthreads() guards cmin reuse
    }

    // backward: min over b complete -> sqrt + block sum
    float bsum = 0.f;
    #pragma unroll
    for (int i = 0; i < 8; i++)
        #pragma unroll
        for (int j = 0; j < 8; j++) bsum += sqrtf(bmin[i][j]);

    #pragma unroll
    for (int o = 16; o; o >>= 1) bsum += __shfl_xor_sync(0xffffffffu, bsum, o);
    if ((tid & 31) == 0) red[tid >> 5] = bsum;
    __syncthreads();
    if (tid < 8) {
        float v = red[tid];
        #pragma unroll
        for (int o = 4; o; o >>= 1) v += __shfl_xor_sync(0xffu, v, o);
        if (tid == 0) g_bwd_part[blockIdx.y * gridDim.x + blockIdx.x] = v;
    }
}

// ---------------------------------------------------------------------------
__global__ void final_kernel(float* __restrict__ out) {
    __shared__ float red[256];
    int tid = threadIdx.x;

    float s1 = 0.f;
    for (int i = tid; i < BB * MM; i += 256)
        s1 += sqrtf(__uint_as_float(g_fwd[i]));
    float s2 = 0.f;
    for (int i = tid; i < 32 * 32; i += 256)
        s2 += g_bwd_part[i];

    red[tid] = s1;
    __syncthreads();
    for (int o = 128; o; o >>= 1) {
        if (tid < o) red[tid] += red[tid + o];
        __syncthreads();
    }
    float fwd_sum = red[0];
    __syncthreads();

    red[tid] = s2;
    __syncthreads();
    for (int o = 128; o; o >>= 1) {
        if (tid < o) red[tid] += red[tid + o];
        __syncthreads();
    }

    if (tid == 0)
        out[0] = fwd_sum / (float)(BB * MM) + red[0] / ((float)NN * (float)MM);
}

// ---------------------------------------------------------------------------
extern "C" void kernel_launch(void* const* d_in, const int* in_sizes, int n_in,
                              void* d_out, int out_size) {
    const float* X = (const float*)d_in[0];   // predicted_set (B,N,D)
    const float* Y = (const float*)d_in[1];   // target_set    (B,M,D)

    init_kernel<<<(BB * MM + 255) / 256, 256>>>();
    norms_kernel<<<(BB * NN + BB * MM) * 32 / 256, 256>>>(X, Y);
    dim3 grid(MM / 128, NN / 128);
    chamfer_main<<<grid, 256>>>(X, Y);
    final_kernel<<<1, 256>>>((float*)d_out);
}

// round 2
// speedup vs baseline: 1.0279x; 1.0279x over previous
#include <cuda_runtime.h>
#include <math.h>

#define BB 8
#define NN 4096
#define MM 4096
#define DD 128

#define BK 16
#define PAD  132   // Bs row stride (floats)
#define PAD2 264   // As2 (duplicated) row stride (floats), multiple of 4

typedef unsigned long long u64;

// Scratch (no allocations allowed -> __device__ globals)
__device__ unsigned int g_fwd[BB * MM];        // min over n of clamped squared dist, as uint bits
__device__ float g_x2[BB * NN];
__device__ float g_y2[BB * MM];
__device__ float g_bwd_part[32 * 32];          // per-block backward partial sums
__device__ float g_fwd_part[32];               // stage-A forward partial sums

// ---------------------------------------------------------------------------
__device__ __forceinline__ u64 pack2(float lo, float hi) {
    u64 r;
    asm("mov.b64 %0, {%1,%2};" : "=l"(r) : "f"(lo), "f"(hi));
    return r;
}
__device__ __forceinline__ void unpack2(u64 v, float& lo, float& hi) {
    asm("mov.b64 {%0,%1}, %2;" : "=f"(lo), "=f"(hi) : "l"(v));
}
__device__ __forceinline__ void ffma2(u64& d, u64 a, u64 b) {
    asm("fma.rn.f32x2 %0, %1, %2, %0;" : "+l"(d) : "l"(a), "l"(b));
}

// ---------------------------------------------------------------------------
__global__ void init_kernel() {
    int i = blockIdx.x * blockDim.x + threadIdx.x;
    if (i < BB * MM) g_fwd[i] = 0x7F800000u;   // +inf
}

// One warp per row: sum of squares of 128 floats
__global__ void norms_kernel(const float* __restrict__ X, const float* __restrict__ Y) {
    int w    = (blockIdx.x * blockDim.x + threadIdx.x) >> 5;
    int lane = threadIdx.x & 31;
    const float* p;
    float* dst;
    if (w < BB * NN) {
        p = X + (size_t)w * DD;
        dst = &g_x2[w];
    } else {
        int w2 = w - BB * NN;
        if (w2 >= BB * MM) return;
        p = Y + (size_t)w2 * DD;
        dst = &g_y2[w2];
    }
    float4 v = ((const float4*)p)[lane];
    float s = v.x * v.x + v.y * v.y + v.z * v.z + v.w * v.w;
    #pragma unroll
    for (int o = 16; o; o >>= 1) s += __shfl_xor_sync(0xffffffffu, s, o);
    if (lane == 0) *dst = s;
}

// ---------------------------------------------------------------------------
// Main: per (128n x 128m) tile, loop b=0..7 (flattened with k0), 256 threads,
// 8x8 outputs/thread held as 8x4 packed f32x2 accumulators.
__global__ __launch_bounds__(256, 1) void chamfer_main(const float* __restrict__ X,
                                                       const float* __restrict__ Y) {
    __shared__ float As2[BK * PAD2];          // A tile, each value duplicated
    __shared__ float Bs[BK * PAD];
    __shared__ unsigned int cmin[128];
    __shared__ float red[8];

    const int tid = threadIdx.x;
    const int tx = tid & 15, ty = tid >> 4;
    const int nTile = blockIdx.y * 128;
    const int mTile = blockIdx.x * 128;

    const int lr  = tid >> 2;   // 0..63 : tile row for loads
    const int lc4 = tid & 3;    // 0..3  : float4 column for loads

    const int n0 = ty * 4, n1 = 64 + ty * 4;
    const int m0 = tx * 4, m1 = 64 + tx * 4;

    float bmin[8][8];
    #pragma unroll
    for (int i = 0; i < 8; i++)
        #pragma unroll
        for (int j = 0; j < 8; j++) bmin[i][j] = INFINITY;

    u64 acc2[8][4];
    #pragma unroll
    for (int i = 0; i < 8; i++)
        #pragma unroll
        for (int j = 0; j < 4; j++) acc2[i][j] = 0ull;

    // prefetch registers for the global->smem pipeline
    float4 pva[2], pvb[2];
    {
        const float* Xb = X + ((size_t)0 * NN + nTile) * DD;
        const float* Yb = Y + ((size_t)0 * MM + mTile) * DD;
        #pragma unroll
        for (int h = 0; h < 2; ++h) {
            int r = lr + h * 64;
            pva[h] = *(const float4*)(Xb + (size_t)r * DD + lc4 * 4);
            pvb[h] = *(const float4*)(Yb + (size_t)r * DD + lc4 * 4);
        }
    }

    // 64 steps = 8 batches x 8 k-tiles
    for (int step = 0; step < 64; ++step) {
        const int b  = step >> 3;

        __syncthreads();   // previous consumers done
        #pragma unroll
        for (int h = 0; h < 2; ++h) {
            int r = lr + h * 64;
            float2 d;
            d.x = pva[h].x; d.y = pva[h].x; *(float2*)&As2[(lc4 * 4 + 0) * PAD2 + 2 * r] = d;
            d.x = pva[h].y; d.y = pva[h].y; *(float2*)&As2[(lc4 * 4 + 1) * PAD2 + 2 * r] = d;
            d.x = pva[h].z; d.y = pva[h].z; *(float2*)&As2[(lc4 * 4 + 2) * PAD2 + 2 * r] = d;
            d.x = pva[h].w; d.y = pva[h].w; *(float2*)&As2[(lc4 * 4 + 3) * PAD2 + 2 * r] = d;
            Bs[(lc4 * 4 + 0) * PAD + r] = pvb[h].x;
            Bs[(lc4 * 4 + 1) * PAD + r] = pvb[h].y;
            Bs[(lc4 * 4 + 2) * PAD + r] = pvb[h].z;
            Bs[(lc4 * 4 + 3) * PAD + r] = pvb[h].w;
        }
        __syncthreads();

        // prefetch next step's global data (overlaps with compute below)
        if (step + 1 < 64) {
            int nb  = (step + 1) >> 3;
            int nk0 = ((step + 1) & 7) * BK;
            const float* Xb = X + ((size_t)nb * NN + nTile) * DD;
            const float* Yb = Y + ((size_t)nb * MM + mTile) * DD;
            #pragma unroll
            for (int h = 0; h < 2; ++h) {
                int r = lr + h * 64;
                pva[h] = *(const float4*)(Xb + (size_t)r * DD + nk0 + lc4 * 4);
                pvb[h] = *(const float4*)(Yb + (size_t)r * DD + nk0 + lc4 * 4);
            }
        }

        #pragma unroll
        for (int kk = 0; kk < BK; ++kk) {
            float4 A0 = *(const float4*)&As2[kk * PAD2 + 2 * n0];
            float4 A1 = *(const float4*)&As2[kk * PAD2 + 2 * n0 + 4];
            float4 A2 = *(const float4*)&As2[kk * PAD2 + 2 * n1];
            float4 A3 = *(const float4*)&As2[kk * PAD2 + 2 * n1 + 4];
            float4 b0 = *(const float4*)&Bs[kk * PAD + m0];
            float4 b1 = *(const float4*)&Bs[kk * PAD + m1];
            u64 a2[8];
            a2[0] = pack2(A0.x, A0.y); a2[1] = pack2(A0.z, A0.w);
            a2[2] = pack2(A1.x, A1.y); a2[3] = pack2(A1.z, A1.w);
            a2[4] = pack2(A2.x, A2.y); a2[5] = pack2(A2.z, A2.w);
            a2[6] = pack2(A3.x, A3.y); a2[7] = pack2(A3.z, A3.w);
            u64 b2[4];
            b2[0] = pack2(b0.x, b0.y); b2[1] = pack2(b0.z, b0.w);
            b2[2] = pack2(b1.x, b1.y); b2[3] = pack2(b1.z, b1.w);
            #pragma unroll
            for (int i = 0; i < 8; i++)
                #pragma unroll
                for (int j = 0; j < 4; j++)
                    ffma2(acc2[i][j], a2[i], b2[j]);
        }

        // end of batch b?  -> epilogue
        if ((step & 7) == 7) {
            __syncthreads();
            if (tid < 128) cmin[tid] = 0x7F800000u;
            __syncthreads();

            float rx2[8], ry2[8];
            #pragma unroll
            for (int i = 0; i < 4; i++) {
                rx2[i]     = g_x2[b * NN + nTile + n0 + i];
                rx2[i + 4] = g_x2[b * NN + nTile + n1 + i];
            }
            #pragma unroll
            for (int j = 0; j < 4; j++) {
                ry2[j]     = g_y2[b * MM + mTile + m0 + j];
                ry2[j + 4] = g_y2[b * MM + mTile + m1 + j];
            }

            float colmin[8];
            #pragma unroll
            for (int j = 0; j < 8; j++) colmin[j] = INFINITY;

            #pragma unroll
            for (int i = 0; i < 8; i++) {
                #pragma unroll
                for (int j2 = 0; j2 < 4; j2++) {
                    float lo, hi;
                    unpack2(acc2[i][j2], lo, hi);
                    int jj = j2 * 2;
                    float d2a = fmaf(-2.f, lo, rx2[i] + ry2[jj]);
                    float d2b = fmaf(-2.f, hi, rx2[i] + ry2[jj + 1]);
                    d2a = fmaxf(d2a, 0.f);
                    d2b = fmaxf(d2b, 0.f);
                    bmin[i][jj]     = fminf(bmin[i][jj], d2a);
                    bmin[i][jj + 1] = fminf(bmin[i][jj + 1], d2b);
                    colmin[jj]      = fminf(colmin[jj], d2a);
                    colmin[jj + 1]  = fminf(colmin[jj + 1], d2b);
                    acc2[i][j2] = 0ull;   // reset for next batch
                }
            }

            #pragma unroll
            for (int j = 0; j < 8; j++) {
                int ml = (j < 4) ? (m0 + j) : (m1 + j - 4);
                atomicMin(&cmin[ml], __float_as_uint(colmin[j]));
            }
            __syncthreads();
            if (tid < 128)
                atomicMin(&g_fwd[(size_t)b * MM + mTile + tid], cmin[tid]);
        }
    }

    // backward: min over b complete -> sqrt + block sum
    float bsum = 0.f;
    #pragma unroll
    for (int i = 0; i < 8; i++)
        #pragma unroll
        for (int j = 0; j < 8; j++) bsum += sqrtf(bmin[i][j]);

    #pragma unroll
    for (int o = 16; o; o >>= 1) bsum += __shfl_xor_sync(0xffffffffu, bsum, o);
    if ((tid & 31) == 0) red[tid >> 5] = bsum;
    __syncthreads();
    if (tid < 8) {
        float v = red[tid];
        #pragma unroll
        for (int o = 4; o; o >>= 1) v += __shfl_xor_sync(0xffu, v, o);
        if (tid == 0) g_bwd_part[blockIdx.y * gridDim.x + blockIdx.x] = v;
    }
}

// ---------------------------------------------------------------------------
// Stage A forward reduction: 32 blocks x 256 threads, 1024 elems each.
__global__ void fwd_reduce_kernel() {
    __shared__ float red[8];
    int tid = threadIdx.x;
    int base = blockIdx.x * 1024;
    float s = 0.f;
    #pragma unroll
    for (int r = 0; r < 4; r++)
        s += sqrtf(__uint_as_float(g_fwd[base + r * 256 + tid]));
    #pragma unroll
    for (int o = 16; o; o >>= 1) s += __shfl_xor_sync(0xffffffffu, s, o);
    if ((tid & 31) == 0) red[tid >> 5] = s;
    __syncthreads();
    if (tid < 8) {
        float v = red[tid];
        #pragma unroll
        for (int o = 4; o; o >>= 1) v += __shfl_xor_sync(0xffu, v, o);
        if (tid == 0) g_fwd_part[blockIdx.x] = v;
    }
}

// ---------------------------------------------------------------------------
__global__ void final_kernel(float* __restrict__ out) {
    __shared__ float red[256];
    int tid = threadIdx.x;

    float s1 = (tid < 32) ? g_fwd_part[tid] : 0.f;
    float s2 = 0.f;
    #pragma unroll
    for (int r = 0; r < 4; r++)
        s2 += g_bwd_part[r * 256 + tid];

    red[tid] = s1;
    __syncthreads();
    for (int o = 128; o; o >>= 1) {
        if (tid < o) red[tid] += red[tid + o];
        __syncthreads();
    }
    float fwd_sum = red[0];
    __syncthreads();

    red[tid] = s2;
    __syncthreads();
    for (int o = 128; o; o >>= 1) {
        if (tid < o) red[tid] += red[tid + o];
        __syncthreads();
    }

    if (tid == 0)
        out[0] = fwd_sum / (float)(BB * MM) + red[0] / ((float)NN * (float)MM);
}

// ---------------------------------------------------------------------------
extern "C" void kernel_launch(void* const* d_in, const int* in_sizes, int n_in,
                              void* d_out, int out_size) {
    const float* X = (const float*)d_in[0];   // predicted_set (B,N,D)
    const float* Y = (const float*)d_in[1];   // target_set    (B,M,D)

    init_kernel<<<(BB * MM + 255) / 256, 256>>>();
    norms_kernel<<<(BB * NN + BB * MM) * 32 / 256, 256>>>(X, Y);
    dim3 grid(MM / 128, NN / 128);
    chamfer_main<<<grid, 256>>>(X, Y);
    fwd_reduce_kernel<<<32, 256>>>();
    final_kernel<<<1, 256>>>((float*)d_out);
}